// round 9
// baseline (speedup 1.0000x reference)
#include <cuda_runtime.h>
#include <cstdint>

// ---------------- problem constants ----------------
#define EDGES   262144
#define NNODES  32768
#define DD      128
#define FFH     512
#define LAYERS  2
#define KCAT    384

#define WT_PER_LAYER 294912

// ---------------- scratch ----------------
__device__ float g_edge[EDGES * DD];
__device__ float g_agg [NNODES * DD];
__device__ float g_ff  [NNODES * FFH];
__device__ float g_ideg[NNODES];
__device__ float g_wt  [LAYERS * WT_PER_LAYER];

enum { EPI_RELU = 0, EPI_ATOMIC = 1, EPI_LNRES = 2 };

#define APITCH 36              // pitch (floats) of one 32-k operand chunk
#define HROW   146             // row stride (floats) of 4-chunk activation buf
static const int TILE_BYTES = 128 * APITCH * 4;     // 18432
static const int HA_BYTES   = 128 * HROW * 4;       // 74752
static const int DYN_MLP    = HA_BYTES + 2 * TILE_BYTES + 1024;   // 112640
static const int DYN_GEMM   = 4 * TILE_BYTES + 1024;              // 74752

// ---------------- device helpers ----------------
__device__ __forceinline__ float totf32(float x) {
    uint32_t t; asm("cvt.rna.tf32.f32 %0, %1;" : "=r"(t) : "f"(x));
    return __uint_as_float(t);
}
__device__ __forceinline__ void mma8(float* d, uint32_t a0, uint32_t a1,
                                     uint32_t a2, uint32_t a3,
                                     uint32_t b0, uint32_t b1) {
    asm volatile(
        "mma.sync.aligned.m16n8k8.row.col.f32.tf32.tf32.f32 "
        "{%0,%1,%2,%3}, {%4,%5,%6,%7}, {%8,%9}, {%0,%1,%2,%3};"
        : "+f"(d[0]), "+f"(d[1]), "+f"(d[2]), "+f"(d[3])
        : "r"(a0), "r"(a1), "r"(a2), "r"(a3), "r"(b0), "r"(b1));
}
// one 32-k chunk of m16n8k8 MMAs over an MT*16 x 64 warp tile
template <int MT>
__device__ __forceinline__ void chunk_mma(const float* Abase, int apitch,
                                          const float* Bs,
                                          int wm, int wn, int g, int r,
                                          float acc[][8][4]) {
#pragma unroll
    for (int s = 0; s < 4; s++) {
        uint2 al[MT], ah[MT];
#pragma unroll
        for (int mt = 0; mt < MT; mt++) {
            const float* p0 = Abase + (wm + mt * 16 + g) * apitch + r * 8 + 2 * s;
            al[mt] = *(const uint2*)p0;
            ah[mt] = *(const uint2*)(p0 + 8 * apitch);
        }
        uint2 bf[8];
#pragma unroll
        for (int nt = 0; nt < 8; nt++)
            bf[nt] = *(const uint2*)(Bs + (wn + nt * 8 + g) * APITCH + r * 8 + 2 * s);
#pragma unroll
        for (int mt = 0; mt < MT; mt++)
#pragma unroll
            for (int nt = 0; nt < 8; nt++)
                mma8(acc[mt][nt], al[mt].x, ah[mt].x, al[mt].y, ah[mt].y,
                     bf[nt].x, bf[nt].y);
    }
}

// ---------------- fused 3-linear MLP over edges: 4 warps x (64x64) ---------
template <int EPI>
__global__ void __launch_bounds__(128, 2)
mlp3_tc(const float* __restrict__ nodes, const float* __restrict__ eattr,
        const int* __restrict__ srcI, const int* __restrict__ dstI,
        const float* __restrict__ W0t, const float* __restrict__ b0,
        const float* __restrict__ W1t, const float* __restrict__ b1,
        const float* __restrict__ W2t, const float* __restrict__ b2,
        float* __restrict__ out, const float* __restrict__ resid,
        const float* __restrict__ lng, const float* __restrict__ lnb)
{
    extern __shared__ char dyn[];
    char*  basep = (char*)(((uintptr_t)dyn + 1023) & ~(uintptr_t)1023);
    float* HA    = (float*)basep;                       // [128][HROW]
    float* Bs0   = (float*)(basep + HA_BYTES);
    float* Bs1   = (float*)(basep + HA_BYTES + TILE_BYTES);
    float* stage = HA;                                  // reuse, pitch 132

    __shared__ int s_src[128], s_dst[128];

    const int tid  = threadIdx.x;
    const int wid  = tid >> 5;
    const int lane = tid & 31;
    const int g    = lane >> 2;
    const int r    = lane & 3;
    const int wm   = (wid >> 1) * 64;   // M band (0 or 64)
    const int wn   = (wid & 1) * 64;    // N band (0 or 64)
    const int m0   = blockIdx.x * 128;

    s_src[tid] = srcI[m0 + tid];
    s_dst[tid] = dstI[m0 + tid];
    __syncthreads();

    float acc[4][8][4];
#pragma unroll
    for (int mt = 0; mt < 4; mt++)
#pragma unroll
        for (int nt = 0; nt < 8; nt++)
#pragma unroll
            for (int q = 0; q < 4; q++) acc[mt][nt][q] = 0.f;

    int arow[8], acol[8];
#pragma unroll
    for (int i = 0; i < 8; i++) {
        int f4 = tid + i * 128;
        arow[i] = f4 >> 3;
        acol[i] = f4 & 7;
    }

    // gather one 32-k chunk of the concat into HA slot (c&3)
    auto loadA = [&](int c) {
        int k0 = c * 32;
        float* slot = HA + (c & 3) * APITCH;
#pragma unroll
        for (int i = 0; i < 8; i++) {
            const float* ap;
            if (k0 < 128)      ap = nodes + (size_t)s_src[arow[i]] * 128 + k0 + acol[i] * 4;
            else if (k0 < 256) ap = eattr + (size_t)(m0 + arow[i]) * 128 + (k0 - 128) + acol[i] * 4;
            else               ap = nodes + (size_t)s_dst[arow[i]] * 128 + (k0 - 256) + acol[i] * 4;
            float4 v = *(const float4*)ap;
            float* arp = slot + arow[i] * HROW;
            arp[ 0 + acol[i]] = totf32(v.x);
            arp[ 8 + acol[i]] = totf32(v.y);
            arp[16 + acol[i]] = totf32(v.z);
            arp[24 + acol[i]] = totf32(v.w);
        }
    };
    auto loadB = [&](const float* Wt, int Kdim, int c, float* Bbuf) {
#pragma unroll
        for (int i = 0; i < 8; i++)
            *(float4*)(Bbuf + arow[i] * APITCH + acol[i] * 4) =
                *(const float4*)(Wt + (size_t)arow[i] * Kdim + c * 32 + acol[i] * 4);
    };
    // acc -> HA (bias + relu + tf32, k-permuted), then zero acc
    auto wbRelu = [&](const float* bias) {
#pragma unroll
        for (int mt = 0; mt < 4; mt++)
#pragma unroll
            for (int q = 0; q < 4; q++) {
                int row = wm + mt * 16 + g + ((q & 2) ? 8 : 0);
#pragma unroll
                for (int nt = 0; nt < 8; nt++) {
                    int col = wn + nt * 8 + 2 * r + (q & 1);
                    float v = fmaxf(acc[mt][nt][q] + __ldg(bias + col), 0.f);
                    int kk = col & 31;
                    HA[row * HROW + (col >> 5) * APITCH + (kk & 3) * 8 + (kk >> 2)]
                        = totf32(v);
                    acc[mt][nt][q] = 0.f;
                }
            }
    };

    // ---- stage 0: K = 384, two 32-k chunks per sync window ----
    for (int c = 0; c < 12; c += 2) {
        loadA(c);
        loadA(c + 1);
        loadB(W0t, KCAT, c, Bs0);
        loadB(W0t, KCAT, c + 1, Bs1);
        __syncthreads();
        chunk_mma<4>(HA + (c & 3) * APITCH, HROW, Bs0, wm, wn, g, r, acc);
        chunk_mma<4>(HA + ((c + 1) & 3) * APITCH, HROW, Bs1, wm, wn, g, r, acc);
        __syncthreads();
    }
    wbRelu(b0);
    __syncthreads();

    // ---- stage 1: K = 128, A resident in HA ----
    for (int c = 0; c < 4; c += 2) {
        loadB(W1t, 128, c, Bs0);
        loadB(W1t, 128, c + 1, Bs1);
        __syncthreads();
        chunk_mma<4>(HA + c * APITCH, HROW, Bs0, wm, wn, g, r, acc);
        chunk_mma<4>(HA + (c + 1) * APITCH, HROW, Bs1, wm, wn, g, r, acc);
        __syncthreads();
    }
    wbRelu(b1);
    __syncthreads();

    // ---- stage 2: K = 128 ----
    for (int c = 0; c < 4; c += 2) {
        loadB(W2t, 128, c, Bs0);
        loadB(W2t, 128, c + 1, Bs1);
        __syncthreads();
        chunk_mma<4>(HA + c * APITCH, HROW, Bs0, wm, wn, g, r, acc);
        chunk_mma<4>(HA + (c + 1) * APITCH, HROW, Bs1, wm, wn, g, r, acc);
        __syncthreads();
    }

    // ---- epilogue ----
    if (EPI == EPI_ATOMIC) {
#pragma unroll
        for (int mt = 0; mt < 4; mt++)
#pragma unroll
            for (int q = 0; q < 4; q++) {
                int row = wm + mt * 16 + g + ((q & 2) ? 8 : 0);
#pragma unroll
                for (int nt = 0; nt < 8; nt++) {
                    int col = wn + nt * 8 + 2 * r + (q & 1);
                    stage[row * 132 + col] = acc[mt][nt][q] + __ldg(b2 + col);
                }
            }
        __syncthreads();
        for (int it = 0; it < 32; it++) {
            int f4  = it * 128 + tid;
            int row = f4 >> 5;
            int c4  = f4 & 31;
            float4 v = *(float4*)(stage + row * 132 + c4 * 4);
            float* dbase = out + (size_t)s_dst[row] * 128 + c4 * 4;
            asm volatile("red.global.add.v4.f32 [%0], {%1,%2,%3,%4};"
                         :: "l"(dbase), "f"(v.x), "f"(v.y), "f"(v.z), "f"(v.w)
                         : "memory");
        }
    } else {  // EPI_LNRES: out = LN(resid + acc + b2)
#pragma unroll
        for (int mt = 0; mt < 4; mt++)
#pragma unroll
            for (int q = 0; q < 4; q++) {
                int row = wm + mt * 16 + g + ((q & 2) ? 8 : 0);
#pragma unroll
                for (int nt = 0; nt < 8; nt++) {
                    int col = wn + nt * 8 + 2 * r + (q & 1);
                    stage[row * 132 + col] = acc[mt][nt][q];
                }
            }
        __syncthreads();
        float4 gg  = *(const float4*)(lng + lane * 4);
        float4 bbn = *(const float4*)(lnb + lane * 4);
        float4 bz  = *(const float4*)(b2 + lane * 4);
        for (int rr = wid; rr < 128; rr += 4) {
            float4 res = *(const float4*)(resid + (size_t)(m0 + rr) * 128 + lane * 4);
            float4 d   = *(float4*)(stage + rr * 132 + lane * 4);
            float v0 = res.x + d.x + bz.x, v1 = res.y + d.y + bz.y;
            float v2 = res.z + d.z + bz.z, v3 = res.w + d.w + bz.w;
            float sum = v0 + v1 + v2 + v3;
#pragma unroll
            for (int off = 16; off > 0; off >>= 1)
                sum += __shfl_xor_sync(0xffffffffu, sum, off);
            float mean = sum * (1.0f / 128.0f);
            float d0 = v0 - mean, d1 = v1 - mean, d2 = v2 - mean, d3 = v3 - mean;
            float sq = d0 * d0 + d1 * d1 + d2 * d2 + d3 * d3;
#pragma unroll
            for (int off = 16; off > 0; off >>= 1)
                sq += __shfl_xor_sync(0xffffffffu, sq, off);
            float inv = rsqrtf(sq * (1.0f / 128.0f) + 1e-5f);
            float4 o;
            o.x = d0 * inv * gg.x + bbn.x;
            o.y = d1 * inv * gg.y + bbn.y;
            o.z = d2 * inv * gg.z + bbn.z;
            o.w = d3 * inv * gg.w + bbn.w;
            *(float4*)(out + (size_t)(m0 + rr) * 128 + lane * 4) = o;
        }
    }
}

// ---------------- dense GEMM (feedforward): 8 warps x (32x64) --------------
template <int EPI>
__global__ void __launch_bounds__(256, 2)
gemm_tc(const float* __restrict__ A, int lda, int K,
        const float* __restrict__ Wt, const float* __restrict__ bias,
        float* __restrict__ out, int ldo,
        const float* __restrict__ resid,
        const float* __restrict__ lng, const float* __restrict__ lnb)
{
    extern __shared__ char dyn[];
    char*  base  = (char*)(((uintptr_t)dyn + 1023) & ~(uintptr_t)1023);
    float* As0   = (float*)base;
    float* As1   = (float*)(base + TILE_BYTES);
    float* Bs0   = (float*)(base + 2 * TILE_BYTES);
    float* Bs1   = (float*)(base + 3 * TILE_BYTES);
    float* stage = (float*)base;

    const int tid  = threadIdx.x;
    const int wid  = tid >> 5;
    const int lane = tid & 31;
    const int g    = lane >> 2;
    const int r    = lane & 3;
    const int wm   = (wid & 3) * 32;
    const int wn   = (wid >> 2) * 64;
    const int m0   = blockIdx.x * 128;
    const int n0   = blockIdx.y * 128;

    float acc[2][8][4];
#pragma unroll
    for (int mt = 0; mt < 2; mt++)
#pragma unroll
        for (int nt = 0; nt < 8; nt++)
#pragma unroll
            for (int q = 0; q < 4; q++) acc[mt][nt][q] = 0.f;

    int arow[4], acol[4];
#pragma unroll
    for (int i = 0; i < 4; i++) {
        int f4 = tid + i * 256;
        arow[i] = f4 >> 3;
        acol[i] = f4 & 7;
    }

    auto loadA = [&](int c, float* Abuf) {
#pragma unroll
        for (int i = 0; i < 4; i++) {
            float4 v = *(const float4*)(A + (size_t)(m0 + arow[i]) * lda + c * 32 + acol[i] * 4);
            float* arp = Abuf + arow[i] * APITCH;
            arp[ 0 + acol[i]] = totf32(v.x);
            arp[ 8 + acol[i]] = totf32(v.y);
            arp[16 + acol[i]] = totf32(v.z);
            arp[24 + acol[i]] = totf32(v.w);
        }
    };
    auto loadB = [&](int c, float* Bbuf) {
#pragma unroll
        for (int i = 0; i < 4; i++)
            *(float4*)(Bbuf + arow[i] * APITCH + acol[i] * 4) =
                *(const float4*)(Wt + (size_t)(n0 + arow[i]) * K + c * 32 + acol[i] * 4);
    };

    const int NC = K >> 5;
    for (int c = 0; c < NC; c += 2) {
        loadA(c, As0);
        loadA(c + 1, As1);
        loadB(c, Bs0);
        loadB(c + 1, Bs1);
        __syncthreads();
        chunk_mma<2>(As0, APITCH, Bs0, wm, wn, g, r, acc);
        chunk_mma<2>(As1, APITCH, Bs1, wm, wn, g, r, acc);
        __syncthreads();
    }

#pragma unroll
    for (int mt = 0; mt < 2; mt++) {
        int rw0 = wm + mt * 16 + g;
#pragma unroll
        for (int nt = 0; nt < 8; nt++) {
            int col = wn + nt * 8 + 2 * r;
            *(float2*)(stage + rw0 * 132 + col)       = make_float2(acc[mt][nt][0], acc[mt][nt][1]);
            *(float2*)(stage + (rw0 + 8) * 132 + col) = make_float2(acc[mt][nt][2], acc[mt][nt][3]);
        }
    }
    __syncthreads();

    if (EPI == EPI_RELU) {
        for (int it = 0; it < 16; it++) {
            int f4  = it * 256 + tid;
            int row = f4 >> 5;
            int c4  = f4 & 31;
            float4 v  = *(float4*)(stage + row * 132 + c4 * 4);
            float4 bb = *(const float4*)(bias + n0 + c4 * 4);
            v.x = fmaxf(v.x + bb.x, 0.f); v.y = fmaxf(v.y + bb.y, 0.f);
            v.z = fmaxf(v.z + bb.z, 0.f); v.w = fmaxf(v.w + bb.w, 0.f);
            *(float4*)(out + (size_t)(m0 + row) * ldo + n0 + c4 * 4) = v;
        }
    } else {  // EPI_LNRES
        float4 gg  = *(const float4*)(lng + lane * 4);
        float4 bbn = *(const float4*)(lnb + lane * 4);
        float4 bz  = *(const float4*)(bias + lane * 4);
        for (int rr = wid; rr < 128; rr += 8) {
            float4 res = *(const float4*)(resid + (size_t)(m0 + rr) * 128 + lane * 4);
            float4 d   = *(float4*)(stage + rr * 132 + lane * 4);
            float v0 = res.x + d.x + bz.x, v1 = res.y + d.y + bz.y;
            float v2 = res.z + d.z + bz.z, v3 = res.w + d.w + bz.w;
            float sum = v0 + v1 + v2 + v3;
#pragma unroll
            for (int off = 16; off > 0; off >>= 1)
                sum += __shfl_xor_sync(0xffffffffu, sum, off);
            float mean = sum * (1.0f / 128.0f);
            float d0 = v0 - mean, d1 = v1 - mean, d2 = v2 - mean, d3 = v3 - mean;
            float sq = d0 * d0 + d1 * d1 + d2 * d2 + d3 * d3;
#pragma unroll
            for (int off = 16; off > 0; off >>= 1)
                sq += __shfl_xor_sync(0xffffffffu, sq, off);
            float inv = rsqrtf(sq * (1.0f / 128.0f) + 1e-5f);
            float4 o;
            o.x = d0 * inv * gg.x + bbn.x;
            o.y = d1 * inv * gg.y + bbn.y;
            o.z = d2 * inv * gg.z + bbn.z;
            o.w = d3 * inv * gg.w + bbn.w;
            *(float4*)(out + (size_t)(m0 + rr) * 128 + lane * 4) = o;
        }
    }
}

// ---------------- standalone LayerNorm (norm0) ----------------
__global__ void ln_k(float* __restrict__ io, const float* __restrict__ add,
                     const float* __restrict__ scale,
                     const float* __restrict__ g, const float* __restrict__ b,
                     int rows)
{
    int row  = blockIdx.x * 8 + (threadIdx.x >> 5);
    int lane = threadIdx.x & 31;
    if (row >= rows) return;
    float s = scale ? scale[row] : 1.0f;

    float4 x = *(const float4*)(io  + (size_t)row * 128 + lane * 4);
    float4 a = *(const float4*)(add + (size_t)row * 128 + lane * 4);
    float v[4] = { x.x + a.x * s, x.y + a.y * s, x.z + a.z * s, x.w + a.w * s };

    float sum = v[0] + v[1] + v[2] + v[3];
#pragma unroll
    for (int off = 16; off > 0; off >>= 1) sum += __shfl_xor_sync(0xffffffffu, sum, off);
    float mean = sum * (1.0f / 128.0f);
    float sq = 0.f;
#pragma unroll
    for (int j = 0; j < 4; j++) { float d = v[j] - mean; sq += d * d; }
#pragma unroll
    for (int off = 16; off > 0; off >>= 1) sq += __shfl_xor_sync(0xffffffffu, sq, off);
    float inv = rsqrtf(sq * (1.0f / 128.0f) + 1e-5f);

    float4 gg = *(const float4*)(g + lane * 4);
    float4 bb = *(const float4*)(b + lane * 4);
    float4 o;
    o.x = (v[0] - mean) * inv * gg.x + bb.x;
    o.y = (v[1] - mean) * inv * gg.y + bb.y;
    o.z = (v[2] - mean) * inv * gg.z + bb.z;
    o.w = (v[3] - mean) * inv * gg.w + bb.w;
    *(float4*)(io + (size_t)row * 128 + lane * 4) = o;
}

// -------- ALL weight transposes (tf32 + k-permute) in ONE launch ------------
__global__ void wt_all(float* __restrict__ wt,
    const float* __restrict__ mW0, const float* __restrict__ mW1,
    const float* __restrict__ mW2, const float* __restrict__ fW0,
    const float* __restrict__ fW1, const float* __restrict__ xW0,
    const float* __restrict__ xW1, const float* __restrict__ xW2)
{
    int seg = blockIdx.y & 7, l = blockIdx.y >> 3;
    int K, N, ofs; const float* src;
    switch (seg) {
      case 0: K=KCAT; N=DD;  ofs=0;      src=mW0 + (size_t)l*KCAT*DD; break;
      case 1: K=DD;   N=DD;  ofs=49152;  src=mW1 + (size_t)l*DD*DD;  break;
      case 2: K=DD;   N=DD;  ofs=65536;  src=mW2 + (size_t)l*DD*DD;  break;
      case 3: K=DD;   N=FFH; ofs=81920;  src=fW0 + (size_t)l*DD*FFH; break;
      case 4: K=FFH;  N=DD;  ofs=147456; src=fW1 + (size_t)l*FFH*DD; break;
      case 5: K=KCAT; N=DD;  ofs=212992; src=xW0 + (size_t)l*KCAT*DD; break;
      case 6: K=DD;   N=DD;  ofs=262144; src=xW1 + (size_t)l*DD*DD;  break;
      default:K=DD;   N=DD;  ofs=278528; src=xW2 + (size_t)l*DD*DD;  break;
    }
    float* dst = wt + (size_t)l * WT_PER_LAYER + ofs;
    int total = K * N;
    for (int i = blockIdx.x * blockDim.x + threadIdx.x; i < total;
         i += gridDim.x * blockDim.x) {
        int n = i / K, rem = i - n * K;
        int c = rem >> 5, p = rem & 31;
        int k = c * 32 + ((p & 7) << 2) + (p >> 3);
        dst[i] = totf32(src[(size_t)k * N + n]);
    }
}

// ---------------- small helpers ----------------
__global__ void copy_k(float4* __restrict__ d, const float4* __restrict__ s, int n4) {
    for (int i = blockIdx.x * blockDim.x + threadIdx.x; i < n4; i += gridDim.x * blockDim.x)
        d[i] = s[i];
}
__global__ void zero_k(float4* __restrict__ p, int n4) {
    for (int i = blockIdx.x * blockDim.x + threadIdx.x; i < n4; i += gridDim.x * blockDim.x)
        p[i] = make_float4(0.f, 0.f, 0.f, 0.f);
}
__global__ void deg_k(const int* __restrict__ dst, float* __restrict__ deg) {
    int e = blockIdx.x * blockDim.x + threadIdx.x;
    if (e < EDGES) atomicAdd(&deg[dst[e]], 1.0f);
}
__global__ void invdeg_k(float* __restrict__ deg) {
    int i = blockIdx.x * blockDim.x + threadIdx.x;
    if (i < NNODES) deg[i] = 1.0f / fmaxf(deg[i], 1.0f);
}

// ---------------- launch ----------------
extern "C" void kernel_launch(void* const* d_in, const int* in_sizes, int n_in,
                              void* d_out, int out_size)
{
    const float* x        = (const float*)d_in[0];
    const int*   eidx     = (const int*)  d_in[1];
    const float* eattr_in = (const float*)d_in[2];
    const float* msg_W0 = (const float*)d_in[3];
    const float* msg_b0 = (const float*)d_in[4];
    const float* msg_W1 = (const float*)d_in[5];
    const float* msg_b1 = (const float*)d_in[6];
    const float* msg_W2 = (const float*)d_in[7];
    const float* msg_b2 = (const float*)d_in[8];
    const float* n0g    = (const float*)d_in[9];
    const float* n0b    = (const float*)d_in[10];
    const float* ff_W0  = (const float*)d_in[11];
    const float* ff_b0  = (const float*)d_in[12];
    const float* ff_W1  = (const float*)d_in[13];
    const float* ff_b1  = (const float*)d_in[14];
    const float* n1g    = (const float*)d_in[15];
    const float* n1b    = (const float*)d_in[16];
    const float* eW0    = (const float*)d_in[17];
    const float* eb0    = (const float*)d_in[18];
    const float* eW1    = (const float*)d_in[19];
    const float* eb1    = (const float*)d_in[20];
    const float* eW2    = (const float*)d_in[21];
    const float* eb2    = (const float*)d_in[22];
    const float* eng    = (const float*)d_in[23];
    const float* enb    = (const float*)d_in[24];

    float* nodes = (float*)d_out;
    const int* src = eidx;
    const int* dst = eidx + EDGES;

    static bool init = false;
    static float *edge, *agg, *ffb, *ideg, *wt;
    if (!init) {
        cudaGetSymbolAddress((void**)&edge, g_edge);
        cudaGetSymbolAddress((void**)&agg,  g_agg);
        cudaGetSymbolAddress((void**)&ffb,  g_ff);
        cudaGetSymbolAddress((void**)&ideg, g_ideg);
        cudaGetSymbolAddress((void**)&wt,   g_wt);
        cudaFuncSetAttribute(mlp3_tc<EPI_ATOMIC>,
                             cudaFuncAttributeMaxDynamicSharedMemorySize, DYN_MLP);
        cudaFuncSetAttribute(mlp3_tc<EPI_LNRES>,
                             cudaFuncAttributeMaxDynamicSharedMemorySize, DYN_MLP);
        cudaFuncSetAttribute(gemm_tc<EPI_RELU>,
                             cudaFuncAttributeMaxDynamicSharedMemorySize, DYN_GEMM);
        cudaFuncSetAttribute(gemm_tc<EPI_LNRES>,
                             cudaFuncAttributeMaxDynamicSharedMemorySize, DYN_GEMM);
        init = true;
    }

    // launches 0..4 (so launch #5 — ncu's -s 5 capture — is mlp3_tc)
    copy_k<<<2048, 256>>>((float4*)nodes, (const float4*)x, NNODES * DD / 4);        // 0
    copy_k<<<4096, 256>>>((float4*)edge, (const float4*)eattr_in, EDGES * DD / 4);   // 1
    wt_all<<<dim3(64, 16), 256>>>(wt, msg_W0, msg_W1, msg_W2, ff_W0, ff_W1,
                                  eW0, eW1, eW2);                                    // 2

    const dim3 gE(EDGES / 128, 1), gN(NNODES / 128, 1), gF(NNODES / 128, FFH / 128);

    for (int l = 0; l < LAYERS; l++) {
        float* wl = wt + (size_t)l * WT_PER_LAYER;
        const int O_MW0 = 0, O_MW1 = 49152, O_MW2 = 65536, O_FW0 = 81920,
                  O_FW1 = 147456, O_EW0 = 212992, O_EW1 = 262144, O_EW2 = 278528;

        // --- fused message MLP + mean aggregation ---
        zero_k<<<4096, 256>>>((float4*)agg, NNODES * DD / 4);                        // 3
        if (l == 0) zero_k<<<64, 256>>>((float4*)ideg, NNODES / 4);                  // 4
        mlp3_tc<EPI_ATOMIC><<<gE, 128, DYN_MLP>>>(                                   // 5 <- ncu
            nodes, edge, src, dst,
            wl + O_MW0, msg_b0 + l * DD, wl + O_MW1, msg_b1 + l * DD,
            wl + O_MW2, msg_b2 + l * DD,
            agg, nullptr, nullptr, nullptr);
        if (l == 0) {
            deg_k<<<EDGES / 256, 256>>>(dst, ideg);
            invdeg_k<<<NNODES / 256, 256>>>(ideg);
        }
        ln_k<<<NNODES / 8, 256>>>(nodes, agg, ideg, n0g + l * DD, n0b + l * DD, NNODES);

        // --- feedforward (norm1 fused into FF2 epilogue) ---
        gemm_tc<EPI_RELU><<<gF, 256, DYN_GEMM>>>(
            nodes, DD, DD, wl + O_FW0, ff_b0 + l * FFH, ffb, FFH,
            nullptr, nullptr, nullptr);
        gemm_tc<EPI_LNRES><<<gN, 256, DYN_GEMM>>>(
            ffb, FFH, FFH, wl + O_FW1, ff_b1 + l * DD, nodes, DD,
            nodes, n1g + l * DD, n1b + l * DD);

        // --- fused edge MLP + residual LayerNorm ---
        mlp3_tc<EPI_LNRES><<<gE, 128, DYN_MLP>>>(
            nodes, edge, src, dst,
            wl + O_EW0, eb0 + l * DD, wl + O_EW1, eb1 + l * DD,
            wl + O_EW2, eb2 + l * DD,
            edge, edge, eng + l * DD, enb + l * DD);
    }
    // nodes (= d_out) holds the final [B, N, D] result.
}

// round 10
// speedup vs baseline: 1.8116x; 1.8116x over previous
#include <cuda_runtime.h>
#include <cuda_fp16.h>
#include <cstdint>

// ---------------- problem constants ----------------
#define EDGES   262144
#define NNODES  32768
#define DD      128
#define FFH     512
#define LAYERS  2
#define KCAT    384

#define WT_PER_LAYER 294912

// ---------------- scratch ----------------
__device__ float  g_edge[EDGES * DD];
__device__ float  g_agg [NNODES * DD];
__device__ float  g_ff  [NNODES * FFH];
__device__ float  g_ideg[NNODES];
__device__ __half g_wt  [LAYERS * WT_PER_LAYER];

enum { EPI_RELU = 0, EPI_ATOMIC = 1, EPI_LNRES = 2 };

// fp16 tile geometry: one 32-k chunk row = 32 halves (64B data) in 96B pitch
#define TPITCH_H 48            // halves per tile row (96 B)
#define HROW_H   208           // halves per HA row (4 chunks * 48 + pad; 104 words ≡ 8 mod 32)
static const int TILE_BYTES = 128 * TPITCH_H * 2;   // 12288
static const int HA_BYTES   = 128 * HROW_H * 2;     // 53248
static const int STAGE_B    = 128 * 132 * 4;        // 67584
static const int DYN_MLP    = HA_BYTES + 2 * TILE_BYTES + 1024;   // 78848 (>= STAGE_B)
static const int DYN_GEMM   = STAGE_B + 1024;                     // 68608 (>= 4 tiles)

// ---------------- device helpers ----------------
__device__ __forceinline__ void mma16(float* d, uint32_t a0, uint32_t a1,
                                      uint32_t a2, uint32_t a3,
                                      uint32_t b0, uint32_t b1) {
    asm volatile(
        "mma.sync.aligned.m16n8k16.row.col.f32.f16.f16.f32 "
        "{%0,%1,%2,%3}, {%4,%5,%6,%7}, {%8,%9}, {%0,%1,%2,%3};"
        : "+f"(d[0]), "+f"(d[1]), "+f"(d[2]), "+f"(d[3])
        : "r"(a0), "r"(a1), "r"(a2), "r"(a3), "r"(b0), "r"(b1));
}
// one 32-k chunk of m16n8k16 MMAs; A pitch in halves, B pitch = TPITCH_H
template <int MT>
__device__ __forceinline__ void chunk_f16(const __half* A, int apitch,
                                          const __half* B,
                                          int wm, int wn, int g, int r,
                                          float acc[][8][4]) {
#pragma unroll
    for (int s = 0; s < 2; s++) {
        uint2 alo[MT], ahi[MT];
#pragma unroll
        for (int mt = 0; mt < MT; mt++) {
            const __half* p0 = A + (wm + mt * 16 + g) * apitch + s * 16 + r * 4;
            alo[mt] = *(const uint2*)p0;               // a0 (.x), a2 (.y)
            ahi[mt] = *(const uint2*)(p0 + 8 * apitch);// a1 (.x), a3 (.y)
        }
        uint2 bf[8];
#pragma unroll
        for (int nt = 0; nt < 8; nt++)
            bf[nt] = *(const uint2*)(B + (wn + nt * 8 + g) * TPITCH_H + s * 16 + r * 4);
#pragma unroll
        for (int mt = 0; mt < MT; mt++)
#pragma unroll
            for (int nt = 0; nt < 8; nt++)
                mma16(acc[mt][nt], alo[mt].x, ahi[mt].x, alo[mt].y, ahi[mt].y,
                      bf[nt].x, bf[nt].y);
    }
}
// write float4 (4 consecutive k at c4*4) into permuted fp16 tile row
__device__ __forceinline__ void put4(__half* rowp, int c4, float4 v) {
    int s  = c4 >> 2, jm = c4 & 3;
    int p1 = ((jm & 1) << 3) | ((jm >> 1) << 1);      // 0,8,2,10
    __half* b = rowp + s * 16 + p1;
    *(__half2*)b       = __floats2half2_rn(v.x, v.y);
    *(__half2*)(b + 4) = __floats2half2_rn(v.z, v.w);
}

// ---------------- fused 3-linear MLP over edges (fp16, 8 warps x 32x64) ----
template <int EPI>
__global__ void __launch_bounds__(256, 2)
mlp3_tc(const float* __restrict__ nodes, const float* __restrict__ eattr,
        const int* __restrict__ srcI, const int* __restrict__ dstI,
        const __half* __restrict__ W0t, const float* __restrict__ b0,
        const __half* __restrict__ W1t, const float* __restrict__ b1,
        const __half* __restrict__ W2t, const float* __restrict__ b2,
        float* __restrict__ out, const float* __restrict__ resid,
        const float* __restrict__ lng, const float* __restrict__ lnb)
{
    extern __shared__ char dyn[];
    char*   basep = (char*)(((uintptr_t)dyn + 1023) & ~(uintptr_t)1023);
    __half* HA    = (__half*)basep;                      // [128][HROW_H]
    __half* Bs0   = (__half*)(basep + HA_BYTES);
    __half* Bs1   = (__half*)(basep + HA_BYTES + TILE_BYTES);
    float*  stage = (float*)basep;                       // reuse, pitch 132

    __shared__ int s_src[128], s_dst[128];

    const int tid  = threadIdx.x;
    const int wid  = tid >> 5;
    const int lane = tid & 31;
    const int g    = lane >> 2;
    const int r    = lane & 3;
    const int wm   = (wid & 3) * 32;
    const int wn   = (wid >> 2) * 64;
    const int m0   = blockIdx.x * 128;

    if (tid < 128) { s_src[tid] = srcI[m0 + tid]; s_dst[tid] = dstI[m0 + tid]; }
    __syncthreads();

    float acc[2][8][4];
#pragma unroll
    for (int mt = 0; mt < 2; mt++)
#pragma unroll
        for (int nt = 0; nt < 8; nt++)
#pragma unroll
            for (int q = 0; q < 4; q++) acc[mt][nt][q] = 0.f;

    int arow[4], acol[4];
#pragma unroll
    for (int i = 0; i < 4; i++) {
        int f4 = tid + i * 256;
        arow[i] = f4 >> 3;
        acol[i] = f4 & 7;
    }

    // gather one 32-k chunk of the concat into HA slot (c&3), fp16 permuted
    auto loadA = [&](int c) {
        int k0 = c * 32;
        __half* slot = HA + (c & 3) * TPITCH_H;
#pragma unroll
        for (int i = 0; i < 4; i++) {
            const float* ap;
            if (k0 < 128)      ap = nodes + (size_t)s_src[arow[i]] * 128 + k0 + acol[i] * 4;
            else if (k0 < 256) ap = eattr + (size_t)(m0 + arow[i]) * 128 + (k0 - 128) + acol[i] * 4;
            else               ap = nodes + (size_t)s_dst[arow[i]] * 128 + (k0 - 256) + acol[i] * 4;
            put4(slot + arow[i] * HROW_H, acol[i], *(const float4*)ap);
        }
    };
    // weights already fp16+permuted in global: straight 16B row copies
    auto loadB = [&](const __half* Wt, int Kdim, int c, __half* Bbuf) {
#pragma unroll
        for (int i = 0; i < 2; i++) {
            int vec = tid + i * 256;            // 512 x 16B = 128 rows x 64B
            int row = vec >> 2, v4 = vec & 3;
            *(uint4*)((char*)(Bbuf + row * TPITCH_H) + v4 * 16) =
                *(const uint4*)((const char*)(Wt + (size_t)row * Kdim + c * 32) + v4 * 16);
        }
    };
    // acc -> HA (bias + relu, fp16 permuted), zero acc
    auto wbRelu = [&](const float* bias) {
#pragma unroll
        for (int mt = 0; mt < 2; mt++)
#pragma unroll
            for (int q = 0; q < 4; q++) {
                int row = wm + mt * 16 + g + ((q & 2) ? 8 : 0);
#pragma unroll
                for (int nt = 0; nt < 8; nt++) {
                    int col = wn + nt * 8 + 2 * r + (q & 1);
                    float v = fmaxf(acc[mt][nt][q] + __ldg(bias + col), 0.f);
                    int c  = col >> 5, u = col & 31;
                    int s  = u >> 4, uu = u & 15;
                    int rr = (uu & 7) >> 1;
                    int qq = (uu & 1) | ((uu >> 3) << 1);
                    HA[row * HROW_H + c * TPITCH_H + s * 16 + rr * 4 + qq] =
                        __float2half_rn(v);
                    acc[mt][nt][q] = 0.f;
                }
            }
    };

    // ---- stage 0: K = 384, two 32-k chunks per sync window ----
    for (int c = 0; c < 12; c += 2) {
        loadA(c);
        loadA(c + 1);
        loadB(W0t, KCAT, c, Bs0);
        loadB(W0t, KCAT, c + 1, Bs1);
        __syncthreads();
        chunk_f16<2>(HA + (c & 3) * TPITCH_H, HROW_H, Bs0, wm, wn, g, r, acc);
        chunk_f16<2>(HA + ((c + 1) & 3) * TPITCH_H, HROW_H, Bs1, wm, wn, g, r, acc);
        __syncthreads();
    }
    wbRelu(b0);
    __syncthreads();

    // ---- stage 1: K = 128, A resident in HA ----
    for (int c = 0; c < 4; c += 2) {
        loadB(W1t, 128, c, Bs0);
        loadB(W1t, 128, c + 1, Bs1);
        __syncthreads();
        chunk_f16<2>(HA + c * TPITCH_H, HROW_H, Bs0, wm, wn, g, r, acc);
        chunk_f16<2>(HA + (c + 1) * TPITCH_H, HROW_H, Bs1, wm, wn, g, r, acc);
        __syncthreads();
    }
    wbRelu(b1);
    __syncthreads();

    // ---- stage 2: K = 128 ----
    for (int c = 0; c < 4; c += 2) {
        loadB(W2t, 128, c, Bs0);
        loadB(W2t, 128, c + 1, Bs1);
        __syncthreads();
        chunk_f16<2>(HA + c * TPITCH_H, HROW_H, Bs0, wm, wn, g, r, acc);
        chunk_f16<2>(HA + (c + 1) * TPITCH_H, HROW_H, Bs1, wm, wn, g, r, acc);
        __syncthreads();
    }
    __syncthreads();

    // ---- epilogue (fp32 stage, pitch 132) ----
    if (EPI == EPI_ATOMIC) {
#pragma unroll
        for (int mt = 0; mt < 2; mt++)
#pragma unroll
            for (int q = 0; q < 4; q++) {
                int row = wm + mt * 16 + g + ((q & 2) ? 8 : 0);
#pragma unroll
                for (int nt = 0; nt < 8; nt++) {
                    int col = wn + nt * 8 + 2 * r + (q & 1);
                    stage[row * 132 + col] = acc[mt][nt][q] + __ldg(b2 + col);
                }
            }
        __syncthreads();
#pragma unroll
        for (int it = 0; it < 16; it++) {
            int f4  = it * 256 + tid;
            int row = f4 >> 5;
            int c4  = f4 & 31;
            float4 v = *(float4*)(stage + row * 132 + c4 * 4);
            float* dbase = out + (size_t)s_dst[row] * 128 + c4 * 4;
            asm volatile("red.global.add.v4.f32 [%0], {%1,%2,%3,%4};"
                         :: "l"(dbase), "f"(v.x), "f"(v.y), "f"(v.z), "f"(v.w)
                         : "memory");
        }
    } else {  // EPI_LNRES: out = LN(resid + acc + b2)
#pragma unroll
        for (int mt = 0; mt < 2; mt++)
#pragma unroll
            for (int q = 0; q < 4; q++) {
                int row = wm + mt * 16 + g + ((q & 2) ? 8 : 0);
#pragma unroll
                for (int nt = 0; nt < 8; nt++) {
                    int col = wn + nt * 8 + 2 * r + (q & 1);
                    stage[row * 132 + col] = acc[mt][nt][q];
                }
            }
        __syncthreads();
        float4 gg  = *(const float4*)(lng + lane * 4);
        float4 bbn = *(const float4*)(lnb + lane * 4);
        float4 bz  = *(const float4*)(b2 + lane * 4);
        for (int rr = wid; rr < 128; rr += 8) {
            float4 res = *(const float4*)(resid + (size_t)(m0 + rr) * 128 + lane * 4);
            float4 d   = *(float4*)(stage + rr * 132 + lane * 4);
            float v0 = res.x + d.x + bz.x, v1 = res.y + d.y + bz.y;
            float v2 = res.z + d.z + bz.z, v3 = res.w + d.w + bz.w;
            float sum = v0 + v1 + v2 + v3;
#pragma unroll
            for (int off = 16; off > 0; off >>= 1)
                sum += __shfl_xor_sync(0xffffffffu, sum, off);
            float mean = sum * (1.0f / 128.0f);
            float d0 = v0 - mean, d1 = v1 - mean, d2 = v2 - mean, d3 = v3 - mean;
            float sq = d0 * d0 + d1 * d1 + d2 * d2 + d3 * d3;
#pragma unroll
            for (int off = 16; off > 0; off >>= 1)
                sq += __shfl_xor_sync(0xffffffffu, sq, off);
            float inv = rsqrtf(sq * (1.0f / 128.0f) + 1e-5f);
            float4 o;
            o.x = d0 * inv * gg.x + bbn.x;
            o.y = d1 * inv * gg.y + bbn.y;
            o.z = d2 * inv * gg.z + bbn.z;
            o.w = d3 * inv * gg.w + bbn.w;
            *(float4*)(out + (size_t)(m0 + rr) * 128 + lane * 4) = o;
        }
    }
}

// ---------------- dense GEMM (feedforward), fp16 ----------------
template <int EPI>
__global__ void __launch_bounds__(256, 2)
gemm_tc(const float* __restrict__ A, int lda, int K,
        const __half* __restrict__ Wt, const float* __restrict__ bias,
        float* __restrict__ out, int ldo,
        const float* __restrict__ resid,
        const float* __restrict__ lng, const float* __restrict__ lnb)
{
    extern __shared__ char dyn[];
    char*   base  = (char*)(((uintptr_t)dyn + 1023) & ~(uintptr_t)1023);
    __half* As0   = (__half*)base;
    __half* As1   = (__half*)(base + TILE_BYTES);
    __half* Bs0   = (__half*)(base + 2 * TILE_BYTES);
    __half* Bs1   = (__half*)(base + 3 * TILE_BYTES);
    float*  stage = (float*)base;

    const int tid  = threadIdx.x;
    const int wid  = tid >> 5;
    const int lane = tid & 31;
    const int g    = lane >> 2;
    const int r    = lane & 3;
    const int wm   = (wid & 3) * 32;
    const int wn   = (wid >> 2) * 64;
    const int m0   = blockIdx.x * 128;
    const int n0   = blockIdx.y * 128;

    float acc[2][8][4];
#pragma unroll
    for (int mt = 0; mt < 2; mt++)
#pragma unroll
        for (int nt = 0; nt < 8; nt++)
#pragma unroll
            for (int q = 0; q < 4; q++) acc[mt][nt][q] = 0.f;

    int arow[4], acol[4];
#pragma unroll
    for (int i = 0; i < 4; i++) {
        int f4 = tid + i * 256;
        arow[i] = f4 >> 3;
        acol[i] = f4 & 7;
    }

    auto loadA = [&](int c, __half* Abuf) {
#pragma unroll
        for (int i = 0; i < 4; i++) {
            float4 v = *(const float4*)(A + (size_t)(m0 + arow[i]) * lda + c * 32 + acol[i] * 4);
            put4(Abuf + arow[i] * TPITCH_H, acol[i], v);
        }
    };
    auto loadB = [&](int c, __half* Bbuf) {
#pragma unroll
        for (int i = 0; i < 2; i++) {
            int vec = tid + i * 256;
            int row = vec >> 2, v4 = vec & 3;
            *(uint4*)((char*)(Bbuf + row * TPITCH_H) + v4 * 16) =
                *(const uint4*)((const char*)(Wt + (size_t)(n0 + row) * K + c * 32) + v4 * 16);
        }
    };

    const int NC = K >> 5;
    for (int c = 0; c < NC; c += 2) {
        loadA(c, As0);
        loadA(c + 1, As1);
        loadB(c, Bs0);
        loadB(c + 1, Bs1);
        __syncthreads();
        chunk_f16<2>(As0, TPITCH_H, Bs0, wm, wn, g, r, acc);
        chunk_f16<2>(As1, TPITCH_H, Bs1, wm, wn, g, r, acc);
        __syncthreads();
    }

#pragma unroll
    for (int mt = 0; mt < 2; mt++) {
        int rw0 = wm + mt * 16 + g;
#pragma unroll
        for (int nt = 0; nt < 8; nt++) {
            int col = wn + nt * 8 + 2 * r;
            *(float2*)(stage + rw0 * 132 + col)       = make_float2(acc[mt][nt][0], acc[mt][nt][1]);
            *(float2*)(stage + (rw0 + 8) * 132 + col) = make_float2(acc[mt][nt][2], acc[mt][nt][3]);
        }
    }
    __syncthreads();

    if (EPI == EPI_RELU) {
#pragma unroll
        for (int it = 0; it < 16; it++) {
            int f4  = it * 256 + tid;
            int row = f4 >> 5;
            int c4  = f4 & 31;
            float4 v  = *(float4*)(stage + row * 132 + c4 * 4);
            float4 bb = *(const float4*)(bias + n0 + c4 * 4);
            v.x = fmaxf(v.x + bb.x, 0.f); v.y = fmaxf(v.y + bb.y, 0.f);
            v.z = fmaxf(v.z + bb.z, 0.f); v.w = fmaxf(v.w + bb.w, 0.f);
            *(float4*)(out + (size_t)(m0 + row) * ldo + n0 + c4 * 4) = v;
        }
    } else {  // EPI_LNRES
        float4 gg  = *(const float4*)(lng + lane * 4);
        float4 bbn = *(const float4*)(lnb + lane * 4);
        float4 bz  = *(const float4*)(bias + lane * 4);
        for (int rr = wid; rr < 128; rr += 8) {
            float4 res = *(const float4*)(resid + (size_t)(m0 + rr) * 128 + lane * 4);
            float4 d   = *(float4*)(stage + rr * 132 + lane * 4);
            float v0 = res.x + d.x + bz.x, v1 = res.y + d.y + bz.y;
            float v2 = res.z + d.z + bz.z, v3 = res.w + d.w + bz.w;
            float sum = v0 + v1 + v2 + v3;
#pragma unroll
            for (int off = 16; off > 0; off >>= 1)
                sum += __shfl_xor_sync(0xffffffffu, sum, off);
            float mean = sum * (1.0f / 128.0f);
            float d0 = v0 - mean, d1 = v1 - mean, d2 = v2 - mean, d3 = v3 - mean;
            float sq = d0 * d0 + d1 * d1 + d2 * d2 + d3 * d3;
#pragma unroll
            for (int off = 16; off > 0; off >>= 1)
                sq += __shfl_xor_sync(0xffffffffu, sq, off);
            float inv = rsqrtf(sq * (1.0f / 128.0f) + 1e-5f);
            float4 o;
            o.x = d0 * inv * gg.x + bbn.x;
            o.y = d1 * inv * gg.y + bbn.y;
            o.z = d2 * inv * gg.z + bbn.z;
            o.w = d3 * inv * gg.w + bbn.w;
            *(float4*)(out + (size_t)(m0 + rr) * 128 + lane * 4) = o;
        }
    }
}

// ---------------- standalone LayerNorm (norm0) ----------------
__global__ void ln_k(float* __restrict__ io, const float* __restrict__ add,
                     const float* __restrict__ scale,
                     const float* __restrict__ g, const float* __restrict__ b,
                     int rows)
{
    int row  = blockIdx.x * 8 + (threadIdx.x >> 5);
    int lane = threadIdx.x & 31;
    if (row >= rows) return;
    float s = scale ? scale[row] : 1.0f;

    float4 x = *(const float4*)(io  + (size_t)row * 128 + lane * 4);
    float4 a = *(const float4*)(add + (size_t)row * 128 + lane * 4);
    float v[4] = { x.x + a.x * s, x.y + a.y * s, x.z + a.z * s, x.w + a.w * s };

    float sum = v[0] + v[1] + v[2] + v[3];
#pragma unroll
    for (int off = 16; off > 0; off >>= 1) sum += __shfl_xor_sync(0xffffffffu, sum, off);
    float mean = sum * (1.0f / 128.0f);
    float sq = 0.f;
#pragma unroll
    for (int j = 0; j < 4; j++) { float d = v[j] - mean; sq += d * d; }
#pragma unroll
    for (int off = 16; off > 0; off >>= 1) sq += __shfl_xor_sync(0xffffffffu, sq, off);
    float inv = rsqrtf(sq * (1.0f / 128.0f) + 1e-5f);

    float4 gg = *(const float4*)(g + lane * 4);
    float4 bb = *(const float4*)(b + lane * 4);
    float4 o;
    o.x = (v[0] - mean) * inv * gg.x + bb.x;
    o.y = (v[1] - mean) * inv * gg.y + bb.y;
    o.z = (v[2] - mean) * inv * gg.z + bb.z;
    o.w = (v[3] - mean) * inv * gg.w + bb.w;
    *(float4*)(io + (size_t)row * 128 + lane * 4) = o;
}

// ------ ALL weight transposes (fp16 + k-permute) in ONE launch --------------
// dst[n*K + c*32 + s*16 + p] = h( src[k*N+n] ), k = c*32+s*16+u,
// u = 2*(p>>2) + (p&1) + 8*((p&3)>>1)
__global__ void wt_all(__half* __restrict__ wt,
    const float* __restrict__ mW0, const float* __restrict__ mW1,
    const float* __restrict__ mW2, const float* __restrict__ fW0,
    const float* __restrict__ fW1, const float* __restrict__ xW0,
    const float* __restrict__ xW1, const float* __restrict__ xW2)
{
    int seg = blockIdx.y & 7, l = blockIdx.y >> 3;
    int K, N, ofs; const float* src;
    switch (seg) {
      case 0: K=KCAT; N=DD;  ofs=0;      src=mW0 + (size_t)l*KCAT*DD; break;
      case 1: K=DD;   N=DD;  ofs=49152;  src=mW1 + (size_t)l*DD*DD;  break;
      case 2: K=DD;   N=DD;  ofs=65536;  src=mW2 + (size_t)l*DD*DD;  break;
      case 3: K=DD;   N=FFH; ofs=81920;  src=fW0 + (size_t)l*DD*FFH; break;
      case 4: K=FFH;  N=DD;  ofs=147456; src=fW1 + (size_t)l*FFH*DD; break;
      case 5: K=KCAT; N=DD;  ofs=212992; src=xW0 + (size_t)l*KCAT*DD; break;
      case 6: K=DD;   N=DD;  ofs=262144; src=xW1 + (size_t)l*DD*DD;  break;
      default:K=DD;   N=DD;  ofs=278528; src=xW2 + (size_t)l*DD*DD;  break;
    }
    __half* dst = wt + (size_t)l * WT_PER_LAYER + ofs;
    int total = K * N;
    for (int i = blockIdx.x * blockDim.x + threadIdx.x; i < total;
         i += gridDim.x * blockDim.x) {
        int n = i / K, rem = i - n * K;
        int c = rem >> 5, t = rem & 31;
        int s = t >> 4, p = t & 15;
        int rr = p >> 2, q = p & 3;
        int u = 2 * rr + (q & 1) + 8 * (q >> 1);
        int k = c * 32 + s * 16 + u;
        dst[i] = __float2half_rn(src[(size_t)k * N + n]);
    }
}

// ---------------- small helpers ----------------
__global__ void copy_k(float4* __restrict__ d, const float4* __restrict__ s, int n4) {
    for (int i = blockIdx.x * blockDim.x + threadIdx.x; i < n4; i += gridDim.x * blockDim.x)
        d[i] = s[i];
}
__global__ void zero_k(float4* __restrict__ p, int n4) {
    for (int i = blockIdx.x * blockDim.x + threadIdx.x; i < n4; i += gridDim.x * blockDim.x)
        p[i] = make_float4(0.f, 0.f, 0.f, 0.f);
}
__global__ void deg_k(const int* __restrict__ dst, float* __restrict__ deg) {
    int e = blockIdx.x * blockDim.x + threadIdx.x;
    if (e < EDGES) atomicAdd(&deg[dst[e]], 1.0f);
}
__global__ void invdeg_k(float* __restrict__ deg) {
    int i = blockIdx.x * blockDim.x + threadIdx.x;
    if (i < NNODES) deg[i] = 1.0f / fmaxf(deg[i], 1.0f);
}

// ---------------- launch ----------------
extern "C" void kernel_launch(void* const* d_in, const int* in_sizes, int n_in,
                              void* d_out, int out_size)
{
    const float* x        = (const float*)d_in[0];
    const int*   eidx     = (const int*)  d_in[1];
    const float* eattr_in = (const float*)d_in[2];
    const float* msg_W0 = (const float*)d_in[3];
    const float* msg_b0 = (const float*)d_in[4];
    const float* msg_W1 = (const float*)d_in[5];
    const float* msg_b1 = (const float*)d_in[6];
    const float* msg_W2 = (const float*)d_in[7];
    const float* msg_b2 = (const float*)d_in[8];
    const float* n0g    = (const float*)d_in[9];
    const float* n0b    = (const float*)d_in[10];
    const float* ff_W0  = (const float*)d_in[11];
    const float* ff_b0  = (const float*)d_in[12];
    const float* ff_W1  = (const float*)d_in[13];
    const float* ff_b1  = (const float*)d_in[14];
    const float* n1g    = (const float*)d_in[15];
    const float* n1b    = (const float*)d_in[16];
    const float* eW0    = (const float*)d_in[17];
    const float* eb0    = (const float*)d_in[18];
    const float* eW1    = (const float*)d_in[19];
    const float* eb1    = (const float*)d_in[20];
    const float* eW2    = (const float*)d_in[21];
    const float* eb2    = (const float*)d_in[22];
    const float* eng    = (const float*)d_in[23];
    const float* enb    = (const float*)d_in[24];

    float* nodes = (float*)d_out;
    const int* src = eidx;
    const int* dst = eidx + EDGES;

    static bool init = false;
    static float *edge, *agg, *ffb, *ideg;
    static __half* wt;
    if (!init) {
        cudaGetSymbolAddress((void**)&edge, g_edge);
        cudaGetSymbolAddress((void**)&agg,  g_agg);
        cudaGetSymbolAddress((void**)&ffb,  g_ff);
        cudaGetSymbolAddress((void**)&ideg, g_ideg);
        cudaGetSymbolAddress((void**)&wt,   g_wt);
        cudaFuncSetAttribute(mlp3_tc<EPI_ATOMIC>,
                             cudaFuncAttributeMaxDynamicSharedMemorySize, DYN_MLP);
        cudaFuncSetAttribute(mlp3_tc<EPI_LNRES>,
                             cudaFuncAttributeMaxDynamicSharedMemorySize, DYN_MLP);
        cudaFuncSetAttribute(gemm_tc<EPI_RELU>,
                             cudaFuncAttributeMaxDynamicSharedMemorySize, DYN_GEMM);
        cudaFuncSetAttribute(gemm_tc<EPI_LNRES>,
                             cudaFuncAttributeMaxDynamicSharedMemorySize, DYN_GEMM);
        init = true;
    }

    copy_k<<<2048, 256>>>((float4*)nodes, (const float4*)x, NNODES * DD / 4);
    copy_k<<<4096, 256>>>((float4*)edge, (const float4*)eattr_in, EDGES * DD / 4);
    wt_all<<<dim3(64, 16), 256>>>(wt, msg_W0, msg_W1, msg_W2, ff_W0, ff_W1,
                                  eW0, eW1, eW2);

    const dim3 gE(EDGES / 128, 1), gN(NNODES / 128, 1), gF(NNODES / 128, FFH / 128);

    for (int l = 0; l < LAYERS; l++) {
        __half* wl = wt + (size_t)l * WT_PER_LAYER;
        const int O_MW0 = 0, O_MW1 = 49152, O_MW2 = 65536, O_FW0 = 81920,
                  O_FW1 = 147456, O_EW0 = 212992, O_EW1 = 262144, O_EW2 = 278528;

        // --- fused message MLP + mean aggregation ---
        zero_k<<<4096, 256>>>((float4*)agg, NNODES * DD / 4);
        if (l == 0) zero_k<<<64, 256>>>((float4*)ideg, NNODES / 4);
        mlp3_tc<EPI_ATOMIC><<<gE, 256, DYN_MLP>>>(
            nodes, edge, src, dst,
            wl + O_MW0, msg_b0 + l * DD, wl + O_MW1, msg_b1 + l * DD,
            wl + O_MW2, msg_b2 + l * DD,
            agg, nullptr, nullptr, nullptr);
        if (l == 0) {
            deg_k<<<EDGES / 256, 256>>>(dst, ideg);
            invdeg_k<<<NNODES / 256, 256>>>(ideg);
        }
        ln_k<<<NNODES / 8, 256>>>(nodes, agg, ideg, n0g + l * DD, n0b + l * DD, NNODES);

        // --- feedforward (norm1 fused into FF2 epilogue) ---
        gemm_tc<EPI_RELU><<<gF, 256, DYN_GEMM>>>(
            nodes, DD, DD, wl + O_FW0, ff_b0 + l * FFH, ffb, FFH,
            nullptr, nullptr, nullptr);
        gemm_tc<EPI_LNRES><<<gN, 256, DYN_GEMM>>>(
            ffb, FFH, FFH, wl + O_FW1, ff_b1 + l * DD, nodes, DD,
            nodes, n1g + l * DD, n1b + l * DD);

        // --- fused edge MLP + residual LayerNorm ---
        mlp3_tc<EPI_LNRES><<<gE, 256, DYN_MLP>>>(
            nodes, edge, src, dst,
            wl + O_EW0, eb0 + l * DD, wl + O_EW1, eb1 + l * DD,
            wl + O_EW2, eb2 + l * DD,
            edge, edge, eng + l * DD, enb + l * DD);
    }
    // nodes (= d_out) holds the final [B, N, D] result.
}

// round 11
// speedup vs baseline: 2.1914x; 1.2096x over previous
#include <cuda_runtime.h>
#include <cuda_fp16.h>
#include <cstdint>

// ---------------- problem constants ----------------
#define EDGES   262144
#define NNODES  32768
#define DD      128
#define FFH     512
#define LAYERS  2
#define KCAT    384

#define WT_PER_LAYER 294912

// ---------------- scratch ----------------
__device__ float  g_edge[EDGES * DD];
__device__ float  g_agg [NNODES * DD];
__device__ float  g_ff  [NNODES * FFH];
__device__ float  g_ideg[NNODES];
__device__ __half g_wt  [LAYERS * WT_PER_LAYER];

enum { EPI_RELU = 0, EPI_ATOMIC = 1, EPI_LNRES = 2 };

#define TPITCH_H 48            // halves per tile row (96 B)
#define HROW_H   208           // halves per HA row (4 chunks * 48 + pad)
static const int TILE_BYTES = 128 * TPITCH_H * 2;   // 12288
static const int HA_BYTES   = 128 * HROW_H * 2;     // 53248
static const int STAGE_B    = 128 * 132 * 4;        // 67584
static const int DYN_MLP    = HA_BYTES + 2 * TILE_BYTES + 1024;   // 78848
static const int DYN_GEMM   = STAGE_B + 1024;                     // 68608 (>= 4 tiles)

// ---------------- device helpers ----------------
__device__ __forceinline__ void mma16(float* d, uint32_t a0, uint32_t a1,
                                      uint32_t a2, uint32_t a3,
                                      uint32_t b0, uint32_t b1) {
    asm volatile(
        "mma.sync.aligned.m16n8k16.row.col.f32.f16.f16.f32 "
        "{%0,%1,%2,%3}, {%4,%5,%6,%7}, {%8,%9}, {%0,%1,%2,%3};"
        : "+f"(d[0]), "+f"(d[1]), "+f"(d[2]), "+f"(d[3])
        : "r"(a0), "r"(a1), "r"(a2), "r"(a3), "r"(b0), "r"(b1));
}
template <int MT>
__device__ __forceinline__ void chunk_f16(const __half* A, int apitch,
                                          const __half* B,
                                          int wm, int wn, int g, int r,
                                          float acc[][8][4]) {
#pragma unroll
    for (int s = 0; s < 2; s++) {
        uint2 alo[MT], ahi[MT];
#pragma unroll
        for (int mt = 0; mt < MT; mt++) {
            const __half* p0 = A + (wm + mt * 16 + g) * apitch + s * 16 + r * 4;
            alo[mt] = *(const uint2*)p0;
            ahi[mt] = *(const uint2*)(p0 + 8 * apitch);
        }
        uint2 bf[8];
#pragma unroll
        for (int nt = 0; nt < 8; nt++)
            bf[nt] = *(const uint2*)(B + (wn + nt * 8 + g) * TPITCH_H + s * 16 + r * 4);
#pragma unroll
        for (int mt = 0; mt < MT; mt++)
#pragma unroll
            for (int nt = 0; nt < 8; nt++)
                mma16(acc[mt][nt], alo[mt].x, ahi[mt].x, alo[mt].y, ahi[mt].y,
                      bf[nt].x, bf[nt].y);
    }
}
// write float4 (4 consecutive k at c4*4) into permuted fp16 tile row
__device__ __forceinline__ void put4(__half* rowp, int c4, float4 v) {
    int s  = c4 >> 2, jm = c4 & 3;
    int p1 = ((jm & 1) << 3) | ((jm >> 1) << 1);
    __half* b = rowp + s * 16 + p1;
    *(__half2*)b       = __floats2half2_rn(v.x, v.y);
    *(__half2*)(b + 4) = __floats2half2_rn(v.z, v.w);
}

// ---------------- fused 3-linear MLP over edges (fp16, reg-prefetched) -----
template <int EPI>
__global__ void __launch_bounds__(256, 2)
mlp3_tc(const float* __restrict__ nodes, const float* __restrict__ eattr,
        const int* __restrict__ srcI, const int* __restrict__ dstI,
        const __half* __restrict__ W0t, const float* __restrict__ b0,
        const __half* __restrict__ W1t, const float* __restrict__ b1,
        const __half* __restrict__ W2t, const float* __restrict__ b2,
        float* __restrict__ out, const float* __restrict__ resid,
        const float* __restrict__ lng, const float* __restrict__ lnb)
{
    extern __shared__ char dyn[];
    char*   basep = (char*)(((uintptr_t)dyn + 1023) & ~(uintptr_t)1023);
    __half* HA    = (__half*)basep;                      // [128][HROW_H]
    __half* BsA[2] = { (__half*)(basep + HA_BYTES),
                       (__half*)(basep + HA_BYTES + TILE_BYTES) };
    float*  stage = (float*)basep;                       // reuse, pitch 132

    __shared__ int s_src[128], s_dst[128];

    const int tid  = threadIdx.x;
    const int wid  = tid >> 5;
    const int lane = tid & 31;
    const int g    = lane >> 2;
    const int r    = lane & 3;
    const int wm   = (wid & 3) * 32;
    const int wn   = (wid >> 2) * 64;
    const int m0   = blockIdx.x * 128;

    if (tid < 128) { s_src[tid] = srcI[m0 + tid]; s_dst[tid] = dstI[m0 + tid]; }
    __syncthreads();

    float acc[2][8][4];
#pragma unroll
    for (int mt = 0; mt < 2; mt++)
#pragma unroll
        for (int nt = 0; nt < 8; nt++)
#pragma unroll
            for (int q = 0; q < 4; q++) acc[mt][nt][q] = 0.f;

    int arow[4], acol[4];
#pragma unroll
    for (int i = 0; i < 4; i++) {
        int f4 = tid + i * 256;
        arow[i] = f4 >> 3;
        acol[i] = f4 & 7;
    }
    const int brow = tid >> 2, bv4 = tid & 3;    // B: 2 vectors (tid, tid+256)
    const int brow2 = (tid + 256) >> 2, bv42 = (tid + 256) & 3;

    float4 prefA[4];
    uint4  prefB[2];

    auto ldgA = [&](int c) {
        int k0 = c * 32;
#pragma unroll
        for (int i = 0; i < 4; i++) {
            const float* ap;
            if (k0 < 128)      ap = nodes + (size_t)s_src[arow[i]] * 128 + k0 + acol[i] * 4;
            else if (k0 < 256) ap = eattr + (size_t)(m0 + arow[i]) * 128 + (k0 - 128) + acol[i] * 4;
            else               ap = nodes + (size_t)s_dst[arow[i]] * 128 + (k0 - 256) + acol[i] * 4;
            prefA[i] = *(const float4*)ap;
        }
    };
    auto stsA = [&](int c) {
        __half* slot = HA + (c & 3) * TPITCH_H;
#pragma unroll
        for (int i = 0; i < 4; i++)
            put4(slot + arow[i] * HROW_H, acol[i], prefA[i]);
    };
    auto ldgB = [&](const __half* Wt, int Kdim, int c) {
        prefB[0] = *(const uint4*)((const char*)(Wt + (size_t)brow  * Kdim + c * 32) + bv4  * 16);
        prefB[1] = *(const uint4*)((const char*)(Wt + (size_t)brow2 * Kdim + c * 32) + bv42 * 16);
    };
    auto stsB = [&](__half* Bbuf) {
        *(uint4*)((char*)(Bbuf + brow  * TPITCH_H) + bv4  * 16) = prefB[0];
        *(uint4*)((char*)(Bbuf + brow2 * TPITCH_H) + bv42 * 16) = prefB[1];
    };
    auto wbRelu = [&](const float* bias) {
#pragma unroll
        for (int mt = 0; mt < 2; mt++)
#pragma unroll
            for (int q = 0; q < 4; q++) {
                int row = wm + mt * 16 + g + ((q & 2) ? 8 : 0);
#pragma unroll
                for (int nt = 0; nt < 8; nt++) {
                    int col = wn + nt * 8 + 2 * r + (q & 1);
                    float v = fmaxf(acc[mt][nt][q] + __ldg(bias + col), 0.f);
                    int c  = col >> 5, u = col & 31;
                    int s  = u >> 4, uu = u & 15;
                    int rr = (uu & 7) >> 1;
                    int qq = (uu & 1) | ((uu >> 3) << 1);
                    HA[row * HROW_H + c * TPITCH_H + s * 16 + rr * 4 + qq] =
                        __float2half_rn(v);
                    acc[mt][nt][q] = 0.f;
                }
            }
    };

    // ---- stage 0: K = 384, pipelined (ldg c+1 in flight during mma c) ----
    ldgA(0); ldgB(W0t, KCAT, 0);
    for (int c = 0; c < 12; c++) {
        stsA(c);
        stsB(BsA[c & 1]);
        if (c < 11) { ldgA(c + 1); ldgB(W0t, KCAT, c + 1); }
        __syncthreads();
        chunk_f16<2>(HA + (c & 3) * TPITCH_H, HROW_H, BsA[c & 1], wm, wn, g, r, acc);
    }
    __syncthreads();
    wbRelu(b0);

    // ---- stage 1: K = 128, A resident in HA ----
    ldgB(W1t, 128, 0);
    for (int c = 0; c < 4; c++) {
        stsB(BsA[c & 1]);
        if (c < 3) ldgB(W1t, 128, c + 1);
        __syncthreads();
        chunk_f16<2>(HA + c * TPITCH_H, HROW_H, BsA[c & 1], wm, wn, g, r, acc);
    }
    __syncthreads();
    wbRelu(b1);

    // ---- stage 2: K = 128 ----
    ldgB(W2t, 128, 0);
    for (int c = 0; c < 4; c++) {
        stsB(BsA[c & 1]);
        if (c < 3) ldgB(W2t, 128, c + 1);
        __syncthreads();
        chunk_f16<2>(HA + c * TPITCH_H, HROW_H, BsA[c & 1], wm, wn, g, r, acc);
    }
    __syncthreads();

    // ---- epilogue (fp32 stage, pitch 132) ----
    if (EPI == EPI_ATOMIC) {
#pragma unroll
        for (int mt = 0; mt < 2; mt++)
#pragma unroll
            for (int q = 0; q < 4; q++) {
                int row = wm + mt * 16 + g + ((q & 2) ? 8 : 0);
#pragma unroll
                for (int nt = 0; nt < 8; nt++) {
                    int col = wn + nt * 8 + 2 * r + (q & 1);
                    stage[row * 132 + col] = acc[mt][nt][q] + __ldg(b2 + col);
                }
            }
        __syncthreads();
#pragma unroll
        for (int it = 0; it < 16; it++) {
            int f4  = it * 256 + tid;
            int row = f4 >> 5;
            int c4  = f4 & 31;
            float4 v = *(float4*)(stage + row * 132 + c4 * 4);
            float* dbase = out + (size_t)s_dst[row] * 128 + c4 * 4;
            asm volatile("red.global.add.v4.f32 [%0], {%1,%2,%3,%4};"
                         :: "l"(dbase), "f"(v.x), "f"(v.y), "f"(v.z), "f"(v.w)
                         : "memory");
        }
    } else {  // EPI_LNRES: out = LN(resid + acc + b2)
#pragma unroll
        for (int mt = 0; mt < 2; mt++)
#pragma unroll
            for (int q = 0; q < 4; q++) {
                int row = wm + mt * 16 + g + ((q & 2) ? 8 : 0);
#pragma unroll
                for (int nt = 0; nt < 8; nt++) {
                    int col = wn + nt * 8 + 2 * r + (q & 1);
                    stage[row * 132 + col] = acc[mt][nt][q];
                }
            }
        __syncthreads();
        float4 gg  = *(const float4*)(lng + lane * 4);
        float4 bbn = *(const float4*)(lnb + lane * 4);
        float4 bz  = *(const float4*)(b2 + lane * 4);
        for (int rr = wid; rr < 128; rr += 8) {
            float4 res = *(const float4*)(resid + (size_t)(m0 + rr) * 128 + lane * 4);
            float4 d   = *(float4*)(stage + rr * 132 + lane * 4);
            float v0 = res.x + d.x + bz.x, v1 = res.y + d.y + bz.y;
            float v2 = res.z + d.z + bz.z, v3 = res.w + d.w + bz.w;
            float sum = v0 + v1 + v2 + v3;
#pragma unroll
            for (int off = 16; off > 0; off >>= 1)
                sum += __shfl_xor_sync(0xffffffffu, sum, off);
            float mean = sum * (1.0f / 128.0f);
            float d0 = v0 - mean, d1 = v1 - mean, d2 = v2 - mean, d3 = v3 - mean;
            float sq = d0 * d0 + d1 * d1 + d2 * d2 + d3 * d3;
#pragma unroll
            for (int off = 16; off > 0; off >>= 1)
                sq += __shfl_xor_sync(0xffffffffu, sq, off);
            float inv = rsqrtf(sq * (1.0f / 128.0f) + 1e-5f);
            float4 o;
            o.x = d0 * inv * gg.x + bbn.x;
            o.y = d1 * inv * gg.y + bbn.y;
            o.z = d2 * inv * gg.z + bbn.z;
            o.w = d3 * inv * gg.w + bbn.w;
            *(float4*)(out + (size_t)(m0 + rr) * 128 + lane * 4) = o;
        }
    }
}

// ---------------- dense GEMM (feedforward), fp16, reg-prefetched -----------
template <int EPI>
__global__ void __launch_bounds__(256, 2)
gemm_tc(const float* __restrict__ A, int lda, int K,
        const __half* __restrict__ Wt, const float* __restrict__ bias,
        float* __restrict__ out, int ldo,
        const float* __restrict__ resid,
        const float* __restrict__ lng, const float* __restrict__ lnb)
{
    extern __shared__ char dyn[];
    char*   base  = (char*)(((uintptr_t)dyn + 1023) & ~(uintptr_t)1023);
    __half* AsA[2] = { (__half*)base, (__half*)(base + TILE_BYTES) };
    __half* BsA[2] = { (__half*)(base + 2 * TILE_BYTES),
                       (__half*)(base + 3 * TILE_BYTES) };
    float*  stage = (float*)base;

    const int tid  = threadIdx.x;
    const int wid  = tid >> 5;
    const int lane = tid & 31;
    const int g    = lane >> 2;
    const int r    = lane & 3;
    const int wm   = (wid & 3) * 32;
    const int wn   = (wid >> 2) * 64;
    const int m0   = blockIdx.x * 128;
    const int n0   = blockIdx.y * 128;

    float acc[2][8][4];
#pragma unroll
    for (int mt = 0; mt < 2; mt++)
#pragma unroll
        for (int nt = 0; nt < 8; nt++)
#pragma unroll
            for (int q = 0; q < 4; q++) acc[mt][nt][q] = 0.f;

    int arow[4], acol[4];
#pragma unroll
    for (int i = 0; i < 4; i++) {
        int f4 = tid + i * 256;
        arow[i] = f4 >> 3;
        acol[i] = f4 & 7;
    }
    const int brow = tid >> 2, bv4 = tid & 3;
    const int brow2 = (tid + 256) >> 2, bv42 = (tid + 256) & 3;

    float4 prefA[4];
    uint4  prefB[2];

    auto ldgA = [&](int c) {
#pragma unroll
        for (int i = 0; i < 4; i++)
            prefA[i] = *(const float4*)(A + (size_t)(m0 + arow[i]) * lda + c * 32 + acol[i] * 4);
    };
    auto stsA = [&](__half* Abuf) {
#pragma unroll
        for (int i = 0; i < 4; i++)
            put4(Abuf + arow[i] * TPITCH_H, acol[i], prefA[i]);
    };
    auto ldgB = [&](int c) {
        prefB[0] = *(const uint4*)((const char*)(Wt + (size_t)(n0 + brow)  * K + c * 32) + bv4  * 16);
        prefB[1] = *(const uint4*)((const char*)(Wt + (size_t)(n0 + brow2) * K + c * 32) + bv42 * 16);
    };
    auto stsB = [&](__half* Bbuf) {
        *(uint4*)((char*)(Bbuf + brow  * TPITCH_H) + bv4  * 16) = prefB[0];
        *(uint4*)((char*)(Bbuf + brow2 * TPITCH_H) + bv42 * 16) = prefB[1];
    };

    const int NC = K >> 5;
    ldgA(0); ldgB(0);
    for (int c = 0; c < NC; c++) {
        stsA(AsA[c & 1]);
        stsB(BsA[c & 1]);
        if (c + 1 < NC) { ldgA(c + 1); ldgB(c + 1); }
        __syncthreads();
        chunk_f16<2>(AsA[c & 1], TPITCH_H, BsA[c & 1], wm, wn, g, r, acc);
    }
    __syncthreads();

#pragma unroll
    for (int mt = 0; mt < 2; mt++) {
        int rw0 = wm + mt * 16 + g;
#pragma unroll
        for (int nt = 0; nt < 8; nt++) {
            int col = wn + nt * 8 + 2 * r;
            *(float2*)(stage + rw0 * 132 + col)       = make_float2(acc[mt][nt][0], acc[mt][nt][1]);
            *(float2*)(stage + (rw0 + 8) * 132 + col) = make_float2(acc[mt][nt][2], acc[mt][nt][3]);
        }
    }
    __syncthreads();

    if (EPI == EPI_RELU) {
#pragma unroll
        for (int it = 0; it < 16; it++) {
            int f4  = it * 256 + tid;
            int row = f4 >> 5;
            int c4  = f4 & 31;
            float4 v  = *(float4*)(stage + row * 132 + c4 * 4);
            float4 bb = *(const float4*)(bias + n0 + c4 * 4);
            v.x = fmaxf(v.x + bb.x, 0.f); v.y = fmaxf(v.y + bb.y, 0.f);
            v.z = fmaxf(v.z + bb.z, 0.f); v.w = fmaxf(v.w + bb.w, 0.f);
            *(float4*)(out + (size_t)(m0 + row) * ldo + n0 + c4 * 4) = v;
        }
    } else {  // EPI_LNRES
        float4 gg  = *(const float4*)(lng + lane * 4);
        float4 bbn = *(const float4*)(lnb + lane * 4);
        float4 bz  = *(const float4*)(bias + lane * 4);
        for (int rr = wid; rr < 128; rr += 8) {
            float4 res = *(const float4*)(resid + (size_t)(m0 + rr) * 128 + lane * 4);
            float4 d   = *(float4*)(stage + rr * 132 + lane * 4);
            float v0 = res.x + d.x + bz.x, v1 = res.y + d.y + bz.y;
            float v2 = res.z + d.z + bz.z, v3 = res.w + d.w + bz.w;
            float sum = v0 + v1 + v2 + v3;
#pragma unroll
            for (int off = 16; off > 0; off >>= 1)
                sum += __shfl_xor_sync(0xffffffffu, sum, off);
            float mean = sum * (1.0f / 128.0f);
            float d0 = v0 - mean, d1 = v1 - mean, d2 = v2 - mean, d3 = v3 - mean;
            float sq = d0 * d0 + d1 * d1 + d2 * d2 + d3 * d3;
#pragma unroll
            for (int off = 16; off > 0; off >>= 1)
                sq += __shfl_xor_sync(0xffffffffu, sq, off);
            float inv = rsqrtf(sq * (1.0f / 128.0f) + 1e-5f);
            float4 o;
            o.x = d0 * inv * gg.x + bbn.x;
            o.y = d1 * inv * gg.y + bbn.y;
            o.z = d2 * inv * gg.z + bbn.z;
            o.w = d3 * inv * gg.w + bbn.w;
            *(float4*)(out + (size_t)(m0 + rr) * 128 + lane * 4) = o;
        }
    }
}

// ---------------- standalone LayerNorm (norm0) ----------------
__global__ void ln_k(float* __restrict__ io, const float* __restrict__ add,
                     const float* __restrict__ scale,
                     const float* __restrict__ g, const float* __restrict__ b,
                     int rows)
{
    int row  = blockIdx.x * 8 + (threadIdx.x >> 5);
    int lane = threadIdx.x & 31;
    if (row >= rows) return;
    float s = scale ? scale[row] : 1.0f;

    float4 x = *(const float4*)(io  + (size_t)row * 128 + lane * 4);
    float4 a = *(const float4*)(add + (size_t)row * 128 + lane * 4);
    float v[4] = { x.x + a.x * s, x.y + a.y * s, x.z + a.z * s, x.w + a.w * s };

    float sum = v[0] + v[1] + v[2] + v[3];
#pragma unroll
    for (int off = 16; off > 0; off >>= 1) sum += __shfl_xor_sync(0xffffffffu, sum, off);
    float mean = sum * (1.0f / 128.0f);
    float sq = 0.f;
#pragma unroll
    for (int j = 0; j < 4; j++) { float d = v[j] - mean; sq += d * d; }
#pragma unroll
    for (int off = 16; off > 0; off >>= 1) sq += __shfl_xor_sync(0xffffffffu, sq, off);
    float inv = rsqrtf(sq * (1.0f / 128.0f) + 1e-5f);

    float4 gg = *(const float4*)(g + lane * 4);
    float4 bb = *(const float4*)(b + lane * 4);
    float4 o;
    o.x = (v[0] - mean) * inv * gg.x + bb.x;
    o.y = (v[1] - mean) * inv * gg.y + bb.y;
    o.z = (v[2] - mean) * inv * gg.z + bb.z;
    o.w = (v[3] - mean) * inv * gg.w + bb.w;
    *(float4*)(io + (size_t)row * 128 + lane * 4) = o;
}

// ------ ONE fused setup kernel: copies + zeros + weight fp16/permute -------
__global__ void setup_all(
    float4* __restrict__ nodes4, const float4* __restrict__ x4,
    float4* __restrict__ edge4, const float4* __restrict__ eattr4,
    float4* __restrict__ agg4, float4* __restrict__ ideg4,
    __half* __restrict__ wt,
    const float* __restrict__ mW0, const float* __restrict__ mW1,
    const float* __restrict__ mW2, const float* __restrict__ fW0,
    const float* __restrict__ fW1, const float* __restrict__ xW0,
    const float* __restrict__ xW1, const float* __restrict__ xW2)
{
    int segy = blockIdx.y;
    int tid0 = blockIdx.x * blockDim.x + threadIdx.x;
    int nthr = gridDim.x * blockDim.x;
    if (segy == 0) {
        for (int i = tid0; i < NNODES * DD / 4; i += nthr) nodes4[i] = x4[i];
    } else if (segy == 1) {
        for (int i = tid0; i < EDGES * DD / 4; i += nthr) edge4[i] = eattr4[i];
    } else if (segy == 2) {
        float4 z = make_float4(0.f, 0.f, 0.f, 0.f);
        for (int i = tid0; i < NNODES * DD / 4; i += nthr) agg4[i] = z;
    } else if (segy == 3) {
        float4 z = make_float4(0.f, 0.f, 0.f, 0.f);
        for (int i = tid0; i < NNODES / 4; i += nthr) ideg4[i] = z;
    } else {
        int seg = (segy - 4) & 7, l = (segy - 4) >> 3;
        int K, N, ofs; const float* src;
        switch (seg) {
          case 0: K=KCAT; N=DD;  ofs=0;      src=mW0 + (size_t)l*KCAT*DD; break;
          case 1: K=DD;   N=DD;  ofs=49152;  src=mW1 + (size_t)l*DD*DD;  break;
          case 2: K=DD;   N=DD;  ofs=65536;  src=mW2 + (size_t)l*DD*DD;  break;
          case 3: K=DD;   N=FFH; ofs=81920;  src=fW0 + (size_t)l*DD*FFH; break;
          case 4: K=FFH;  N=DD;  ofs=147456; src=fW1 + (size_t)l*FFH*DD; break;
          case 5: K=KCAT; N=DD;  ofs=212992; src=xW0 + (size_t)l*KCAT*DD; break;
          case 6: K=DD;   N=DD;  ofs=262144; src=xW1 + (size_t)l*DD*DD;  break;
          default:K=DD;   N=DD;  ofs=278528; src=xW2 + (size_t)l*DD*DD;  break;
        }
        __half* dst = wt + (size_t)l * WT_PER_LAYER + ofs;
        int total = K * N;
        for (int i = tid0; i < total; i += nthr) {
            int n = i / K, rem = i - n * K;
            int c = rem >> 5, t = rem & 31;
            int s = t >> 4, p = t & 15;
            int rr = p >> 2, q = p & 3;
            int u = 2 * rr + (q & 1) + 8 * (q >> 1);
            int k = c * 32 + s * 16 + u;
            dst[i] = __float2half_rn(src[(size_t)k * N + n]);
        }
    }
}

// ---------------- small helpers ----------------
__global__ void zero_k(float4* __restrict__ p, int n4) {
    for (int i = blockIdx.x * blockDim.x + threadIdx.x; i < n4; i += gridDim.x * blockDim.x)
        p[i] = make_float4(0.f, 0.f, 0.f, 0.f);
}
__global__ void deg_k(const int* __restrict__ dst, float* __restrict__ deg) {
    int e = blockIdx.x * blockDim.x + threadIdx.x;
    if (e < EDGES) atomicAdd(&deg[dst[e]], 1.0f);
}
__global__ void invdeg_k(float* __restrict__ deg) {
    int i = blockIdx.x * blockDim.x + threadIdx.x;
    if (i < NNODES) deg[i] = 1.0f / fmaxf(deg[i], 1.0f);
}

// ---------------- launch ----------------
extern "C" void kernel_launch(void* const* d_in, const int* in_sizes, int n_in,
                              void* d_out, int out_size)
{
    const float* x        = (const float*)d_in[0];
    const int*   eidx     = (const int*)  d_in[1];
    const float* eattr_in = (const float*)d_in[2];
    const float* msg_W0 = (const float*)d_in[3];
    const float* msg_b0 = (const float*)d_in[4];
    const float* msg_W1 = (const float*)d_in[5];
    const float* msg_b1 = (const float*)d_in[6];
    const float* msg_W2 = (const float*)d_in[7];
    const float* msg_b2 = (const float*)d_in[8];
    const float* n0g    = (const float*)d_in[9];
    const float* n0b    = (const float*)d_in[10];
    const float* ff_W0  = (const float*)d_in[11];
    const float* ff_b0  = (const float*)d_in[12];
    const float* ff_W1  = (const float*)d_in[13];
    const float* ff_b1  = (const float*)d_in[14];
    const float* n1g    = (const float*)d_in[15];
    const float* n1b    = (const float*)d_in[16];
    const float* eW0    = (const float*)d_in[17];
    const float* eb0    = (const float*)d_in[18];
    const float* eW1    = (const float*)d_in[19];
    const float* eb1    = (const float*)d_in[20];
    const float* eW2    = (const float*)d_in[21];
    const float* eb2    = (const float*)d_in[22];
    const float* eng    = (const float*)d_in[23];
    const float* enb    = (const float*)d_in[24];

    float* nodes = (float*)d_out;
    const int* src = eidx;
    const int* dst = eidx + EDGES;

    static bool init = false;
    static float *edge, *agg, *ffb, *ideg;
    static __half* wt;
    if (!init) {
        cudaGetSymbolAddress((void**)&edge, g_edge);
        cudaGetSymbolAddress((void**)&agg,  g_agg);
        cudaGetSymbolAddress((void**)&ffb,  g_ff);
        cudaGetSymbolAddress((void**)&ideg, g_ideg);
        cudaGetSymbolAddress((void**)&wt,   g_wt);
        cudaFuncSetAttribute(mlp3_tc<EPI_ATOMIC>,
                             cudaFuncAttributeMaxDynamicSharedMemorySize, DYN_MLP);
        cudaFuncSetAttribute(mlp3_tc<EPI_LNRES>,
                             cudaFuncAttributeMaxDynamicSharedMemorySize, DYN_MLP);
        cudaFuncSetAttribute(gemm_tc<EPI_RELU>,
                             cudaFuncAttributeMaxDynamicSharedMemorySize, DYN_GEMM);
        cudaFuncSetAttribute(gemm_tc<EPI_LNRES>,
                             cudaFuncAttributeMaxDynamicSharedMemorySize, DYN_GEMM);
        init = true;
    }

    // our launch 0..2, so launch 3 (overall skip-5 with the 2 harness
    // pre-launches observed in round 10) is the FIRST mlp3 — ncu target.
    setup_all<<<dim3(256, 20), 256>>>(
        (float4*)nodes, (const float4*)x, (float4*)edge, (const float4*)eattr_in,
        (float4*)agg, (float4*)ideg, wt,
        msg_W0, msg_W1, msg_W2, ff_W0, ff_W1, eW0, eW1, eW2);       // 0
    deg_k<<<EDGES / 256, 256>>>(dst, ideg);                         // 1
    invdeg_k<<<NNODES / 256, 256>>>(ideg);                          // 2

    const dim3 gE(EDGES / 128, 1), gN(NNODES / 128, 1), gF(NNODES / 128, FFH / 128);

    for (int l = 0; l < LAYERS; l++) {
        __half* wl = wt + (size_t)l * WT_PER_LAYER;
        const int O_MW0 = 0, O_MW1 = 49152, O_MW2 = 65536, O_FW0 = 81920,
                  O_FW1 = 147456, O_EW0 = 212992, O_EW1 = 262144, O_EW2 = 278528;

        if (l > 0) zero_k<<<4096, 256>>>((float4*)agg, NNODES * DD / 4);
        mlp3_tc<EPI_ATOMIC><<<gE, 256, DYN_MLP>>>(                   // 3 (l=0) <- ncu
            nodes, edge, src, dst,
            wl + O_MW0, msg_b0 + l * DD, wl + O_MW1, msg_b1 + l * DD,
            wl + O_MW2, msg_b2 + l * DD,
            agg, nullptr, nullptr, nullptr);
        ln_k<<<NNODES / 8, 256>>>(nodes, agg, ideg, n0g + l * DD, n0b + l * DD, NNODES);

        gemm_tc<EPI_RELU><<<gF, 256, DYN_GEMM>>>(
            nodes, DD, DD, wl + O_FW0, ff_b0 + l * FFH, ffb, FFH,
            nullptr, nullptr, nullptr);
        gemm_tc<EPI_LNRES><<<gN, 256, DYN_GEMM>>>(
            ffb, FFH, FFH, wl + O_FW1, ff_b1 + l * DD, nodes, DD,
            nodes, n1g + l * DD, n1b + l * DD);

        mlp3_tc<EPI_LNRES><<<gE, 256, DYN_MLP>>>(
            nodes, edge, src, dst,
            wl + O_EW0, eb0 + l * DD, wl + O_EW1, eb1 + l * DD,
            wl + O_EW2, eb2 + l * DD,
            edge, edge, eng + l * DD, enb + l * DD);
    }
    // nodes (= d_out) holds the final [B, N, D] result.
}